// round 17
// baseline (speedup 1.0000x reference)
#include <cuda_runtime.h>
#include <math.h>

#define NN 50000
#define EE 400000
#define FF 32
#define HALF_E (EE / 2)

typedef unsigned long long ull;

// ---------------- scratch ----------------
// e-feature buffers TRANSPOSED: [FF][EE], element (k, e) at k*EE + e
__device__ __align__(128) float g_e1[(size_t)EE * FF];
__device__ __align__(128) float g_e2[(size_t)EE * FF];
__device__ __align__(128) float g_e3[(size_t)EE * FF];
__device__ __align__(128) float g_acc1[(size_t)NN * FF];
__device__ __align__(128) float g_acc2[(size_t)NN * FF];
__device__ __align__(128) float g_acc3[(size_t)NN * FF];
__device__ __align__(128) float g_uv[(size_t)NN * 64];
__device__ __align__(128) float g_cnt[NN];
__device__ __align__(16) float g_wx[FF * 4];
__device__ __align__(16) float g_bx[4];
__device__ __align__(16) float g_wz[FF];
__device__ float g_bz;

// ---------------- f32x2 helpers ----------------
__device__ __forceinline__ void ffma2(ull& d, ull a, ull b) {
    asm("fma.rn.f32x2 %0, %1, %2, %0;" : "+l"(d) : "l"(a), "l"(b));
}
__device__ __forceinline__ ull pk2(float v) {
    ull r;
    asm("mov.b64 %0, {%1, %1};" : "=l"(r) : "f"(v));
    return r;
}
__device__ __forceinline__ ull mk2(float lo, float hi) {
    ull r;
    asm("mov.b64 %0, {%1, %2};" : "=l"(r) : "f"(lo), "f"(hi));
    return r;
}
__device__ __forceinline__ void un2(ull v, float& lo, float& hi) {
    asm("mov.b64 {%0, %1}, %2;" : "=f"(lo), "=f"(hi) : "l"(v));
}
__device__ __forceinline__ ull add2(ull a, ull b) {
    ull r;
    asm("add.rn.f32x2 %0, %1, %2;" : "=l"(r) : "l"(a), "l"(b));
    return r;
}
union V32 {
    float f[FF];
    ull u[FF / 2];
};

__device__ __forceinline__ void cpsh(float* dst, const float* src, int n, int tid, int nt) {
    for (int i = tid; i < n; i += nt) dst[i] = src[i];
}
__device__ __forceinline__ void ldbias(V32& h, const float* __restrict__ b) {
#pragma unroll
    for (int j = 0; j < FF; j++) h.f[j] = b[j];
}
__device__ __forceinline__ void relu32(V32& h) {
#pragma unroll
    for (int j = 0; j < FF; j++) h.f[j] = fmaxf(h.f[j], 0.f);
}
__device__ __forceinline__ void red4(float* __restrict__ a, float x, float y, float z, float w) {
    asm volatile("red.global.add.v4.f32 [%0], {%1, %2, %3, %4};" ::"l"(a), "f"(x), "f"(y),
                 "f"(z), "f"(w)
                 : "memory");
}
__device__ __forceinline__ void red1(float* __restrict__ a, float v) {
    asm volatile("red.global.add.f32 [%0], %1;" ::"l"(a), "f"(v) : "memory");
}
__device__ __forceinline__ void scatter32(float* __restrict__ acc, const V32& o) {
#pragma unroll
    for (int j = 0; j < FF; j += 4) red4(acc + j, o.f[j], o.f[j + 1], o.f[j + 2], o.f[j + 3]);
}

__device__ __forceinline__ void fmarow1(V32& h, ull v, const float* __restrict__ wr) {
#pragma unroll
    for (int j = 0; j < 8; j++) {
        ulonglong2 w = *(const ulonglong2*)(wr + j * 4);
        ffma2(h.u[2 * j + 0], v, w.x);
        ffma2(h.u[2 * j + 1], v, w.y);
    }
}
__device__ __forceinline__ void fmarow2p(V32& h0, V32& h1, ull v0, ull v1,
                                         const float* __restrict__ wr) {
#pragma unroll
    for (int j = 0; j < 8; j++) {
        ulonglong2 w = *(const ulonglong2*)(wr + j * 4);
        ffma2(h0.u[2 * j + 0], v0, w.x);
        ffma2(h0.u[2 * j + 1], v0, w.y);
        ffma2(h1.u[2 * j + 0], v1, w.x);
        ffma2(h1.u[2 * j + 1], v1, w.y);
    }
}
__device__ __forceinline__ void layer2p(V32& o0, V32& o1, const V32& h0, const V32& h1,
                                        const float* __restrict__ sw1,
                                        const float* __restrict__ sb1) {
    ldbias(o0, sb1);
    ldbias(o1, sb1);
#pragma unroll
    for (int k = 0; k < FF; k++) fmarow2p(o0, o1, pk2(h0.f[k]), pk2(h1.f[k]), sw1 + k * FF);
}
__device__ __forceinline__ void store_relu2T(float* __restrict__ gT, int e0, const V32& o0,
                                             const V32& o1) {
    float* p = gT + e0;
#pragma unroll
    for (int j = 0; j < FF; j++) {
        float2 t = make_float2(fmaxf(o0.f[j], 0.f), fmaxf(o1.f[j], 0.f));
        *(float2*)(p + (size_t)j * EE) = t;
    }
}

// ---------------- init (vectorized) + head fold fused ----------------
__global__ void k_init(const float* __restrict__ beta, float* __restrict__ out,
                       const float* __restrict__ wl01, const float* __restrict__ bl01,
                       const float* __restrict__ wl02, const float* __restrict__ bl02,
                       const float* __restrict__ wl1, const float* __restrict__ bl1,
                       const float* __restrict__ wl2, const float* __restrict__ bl2) {
    int i = blockIdx.x * blockDim.x + threadIdx.x;
    const int NQ = NN * FF / 4;
    float4 z = make_float4(0.f, 0.f, 0.f, 0.f);
    if (i < NQ) {
        ((float4*)g_acc1)[i] = z;
        ((float4*)g_acc2)[i] = z;
        ((float4*)g_acc3)[i] = z;
    }
    if (i < NN) g_cnt[i] = 0.f;
    if (i < 3 * NN) out[(size_t)5 * EE + i] = beta[i];

    if (blockIdx.x == 0) {
        int t = threadIdx.x;
        if (t < 128) {
            int k = t >> 2, j = t & 3;
            float s = 0.f;
#pragma unroll
            for (int m = 0; m < FF; m++) s += wl01[k * FF + m] * wl1[m * 4 + j];
            g_wx[k * 4 + j] = s;
        }
        if (t < 4) {
            float s = bl1[t];
#pragma unroll
            for (int m = 0; m < FF; m++) s += bl01[m] * wl1[m * 4 + t];
            g_bx[t] = s;
        }
        if (t >= 128 && t < 160) {
            int k = t - 128;
            float s = 0.f;
#pragma unroll
            for (int m = 0; m < FF; m++) s += wl02[k * FF + m] * wl2[m];
            g_wz[k] = s;
        }
        if (t == 160) {
            float s = bl2[0];
#pragma unroll
            for (int m = 0; m < FF; m++) s += bl02[m] * wl2[m];
            g_bz = s;
        }
    }
}

// ---------------- node projection (R16 proven) ----------------
template <int KP>
__global__ __launch_bounds__(256) void k_node(const float* __restrict__ acca,
                                              const float* __restrict__ accb,
                                              const float* __restrict__ W0,
                                              const float* __restrict__ b0) {
    __shared__ __align__(16) float s_w[2 * KP * FF];
    __shared__ __align__(16) float s_b[FF];
    int tid = threadIdx.x;
    int n = blockIdx.x * 128 + (tid & 127);
    float cnt = (n < NN) ? g_cnt[n] : 1.0f;
    cpsh(s_w, W0, 2 * KP * FF, tid, 256);
    cpsh(s_b, b0, FF, tid, 256);
    __syncthreads();
    int isV = tid >> 7;
    if (n >= NN) return;
    float inv = 1.0f / fmaxf(cnt, 1.0f);
    const float* ws = s_w + (isV ? KP * FF : 0);
    V32 acc;
    if (isV) {
#pragma unroll
        for (int j = 0; j < FF; j++) acc.f[j] = 0.f;
    } else {
        ldbias(acc, s_b);
    }
    const float* xpa = acca + (size_t)n * FF;
#pragma unroll
    for (int k4 = 0; k4 < 8; k4++) {
        float4 xv = *(const float4*)(xpa + k4 * 4);
        xv.x = fmaxf(xv.x, 0.f) * inv;
        xv.y = fmaxf(xv.y, 0.f) * inv;
        xv.z = fmaxf(xv.z, 0.f) * inv;
        xv.w = fmaxf(xv.w, 0.f) * inv;
        int k = k4 * 4;
        fmarow1(acc, pk2(xv.x), ws + (k + 0) * FF);
        fmarow1(acc, pk2(xv.y), ws + (k + 1) * FF);
        fmarow1(acc, pk2(xv.z), ws + (k + 2) * FF);
        fmarow1(acc, pk2(xv.w), ws + (k + 3) * FF);
    }
    if (KP == 64) {
        const float* xpb = accb + (size_t)n * FF;
#pragma unroll
        for (int k4 = 0; k4 < 8; k4++) {
            float4 xv = *(const float4*)(xpb + k4 * 4);
            xv.x = fmaxf(xv.x, 0.f) * inv;
            xv.y = fmaxf(xv.y, 0.f) * inv;
            xv.z = fmaxf(xv.z, 0.f) * inv;
            xv.w = fmaxf(xv.w, 0.f) * inv;
            int k = 32 + k4 * 4;
            fmarow1(acc, pk2(xv.x), ws + (k + 0) * FF);
            fmarow1(acc, pk2(xv.y), ws + (k + 1) * FF);
            fmarow1(acc, pk2(xv.z), ws + (k + 2) * FF);
            fmarow1(acc, pk2(xv.w), ws + (k + 3) * FF);
        }
    }
    float* up = g_uv + (size_t)n * 64 + isV * 32;
#pragma unroll
    for (int j = 0; j < FF; j += 4) *(float4*)(up + j) = *(float4*)(acc.f + j);
}

// ---------------- conv1 (R16 proven pair) ----------------
__global__ __launch_bounds__(128) void k_conv1(const float* __restrict__ ea,
                                               const int* __restrict__ eidx,
                                               const float* __restrict__ w10,
                                               const float* __restrict__ b10,
                                               const float* __restrict__ w11,
                                               const float* __restrict__ b11) {
    __shared__ __align__(16) float s_w0[4 * FF];
    __shared__ __align__(16) float s_b0[FF];
    __shared__ __align__(16) float s_w1[FF * FF];
    __shared__ __align__(16) float s_b1[FF];
    int tid = threadIdx.x, nt = blockDim.x;
    int p = blockIdx.x * nt + tid;
    bool act = p < HALF_E;
    int e0 = 2 * p, e1 = 2 * p + 1;
    float4 a0, a1;
    int r0 = 0, r1 = 0;
    if (act) {
        a0 = *(const float4*)(ea + (size_t)e0 * 4);
        a1 = *(const float4*)(ea + (size_t)e1 * 4);
        r0 = eidx[e0];
        r1 = eidx[e1];
    }
    cpsh(s_w0, w10, 4 * FF, tid, nt);
    cpsh(s_b0, b10, FF, tid, nt);
    cpsh(s_w1, w11, FF * FF, tid, nt);
    cpsh(s_b1, b11, FF, tid, nt);
    __syncthreads();
    if (!act) return;
    V32 h0, h1;
    ldbias(h0, s_b0);
    ldbias(h1, s_b0);
    fmarow2p(h0, h1, pk2(a0.x), pk2(a1.x), s_w0);
    fmarow2p(h0, h1, pk2(a0.y), pk2(a1.y), s_w0 + FF);
    fmarow2p(h0, h1, pk2(a0.z), pk2(a1.z), s_w0 + 2 * FF);
    fmarow2p(h0, h1, pk2(a0.w), pk2(a1.w), s_w0 + 3 * FF);
    relu32(h0);
    relu32(h1);
    V32 o0, o1;
    layer2p(o0, o1, h0, h1, s_w1, s_b1);
    scatter32(g_acc1 + (size_t)r0 * FF, o0);
    scatter32(g_acc1 + (size_t)r1 * FF, o1);
    atomicAdd(&g_cnt[r0], 1.0f);
    atomicAdd(&g_cnt[r1], 1.0f);
    store_relu2T(g_e1, e0, o0, o1);
}

// ============ column-ownership warp edge kernel ============
// lane j owns output column j; weights in lane registers.
// warp handles 32 edges; pass t handles edges (base+2t, base+2t+1).
// MODE 0: edge2 (K1=36: rows 0-3 ea, 4-35 e1)
// MODE 1: edge3 (K1=64: 0-31 e2, 32-63 e1), MODE 2: edge4 + heads
#define SXP 36  // smem row stride (floats)

template <int K1, int MODE>
__global__ __launch_bounds__(128) void k_edgew(
    const int* __restrict__ eidx, const float* __restrict__ ea,
    const float* __restrict__ srcA, const float* __restrict__ srcB,
    const float* __restrict__ W0e, const float* __restrict__ W1,
    const float* __restrict__ b1, float* __restrict__ accout, float* __restrict__ eout,
    float* __restrict__ out) {
    extern __shared__ float sm[];
    const int WSX = K1 * SXP;
    const int WSO = 32 * SXP;
    const int WS = WSX + WSO + 64 + 64;  // Xs, obuf, hbuf(64), idx(64)
    int warp = threadIdx.x >> 5, lane = threadIdx.x & 31;
    float* Xs = sm + warp * WS;
    float* obuf = Xs + WSX;
    float* hbuf = obuf + WSO;
    int* idxs = (int*)(hbuf + 64);

    int base = (blockIdx.x * 4 + warp) * 32;

    // weights -> registers (coalesced)
    float w0r[K1], w1r[32];
#pragma unroll
    for (int k = 0; k < K1; k++) w0r[k] = W0e[k * 32 + lane];
#pragma unroll
    for (int k = 0; k < 32; k++) w1r[k] = W1[k * 32 + lane];
    float b1j = b1[lane];

    // stage edge indices
    idxs[lane] = eidx[base + lane];
    idxs[32 + lane] = eidx[EE + base + lane];

    // stage X tile [K1][32]
    if (MODE == 0) {
        float4 a = *(const float4*)(ea + (size_t)(base + lane) * 4);
        Xs[0 * SXP + lane] = a.x;
        Xs[1 * SXP + lane] = a.y;
        Xs[2 * SXP + lane] = a.z;
        Xs[3 * SXP + lane] = a.w;
#pragma unroll
        for (int i = 0; i < 8; i++) {
            int row = 4 * i + (lane >> 3);
            int col = (lane & 7) * 4;
            float4 v = *(const float4*)(srcA + (size_t)row * EE + base + col);
            *(float4*)(Xs + (4 + row) * SXP + col) = v;
        }
    } else {
#pragma unroll
        for (int i = 0; i < 16; i++) {
            int row = 4 * i + (lane >> 3);
            int col = (lane & 7) * 4;
            const float* s =
                (row < 32) ? srcA + (size_t)row * EE : srcB + (size_t)(row - 32) * EE;
            float4 v = *(const float4*)(s + base + col);
            *(float4*)(Xs + row * SXP + col) = v;
        }
    }
    __syncwarp();

    for (int t = 0; t < 16; t++) {
        int r0 = idxs[2 * t], r1 = idxs[2 * t + 1];
        int c0 = idxs[32 + 2 * t], c1 = idxs[32 + 2 * t + 1];
        float u0 = g_uv[(size_t)r0 * 64 + lane] + g_uv[(size_t)c0 * 64 + 32 + lane];
        float u1 = g_uv[(size_t)r1 * 64 + lane] + g_uv[(size_t)c1 * 64 + 32 + lane];
        ull aa = mk2(u0, u1);
        ull ab = 0;
        // layer1: h[j] = UV[j] + sum_k x[k] * w0[k][j]
#pragma unroll
        for (int k = 0; k < K1; k += 2) {
            ull x0 = *(const ull*)(Xs + k * SXP + 2 * t);
            ffma2(aa, x0, pk2(w0r[k]));
            ull x1 = *(const ull*)(Xs + (k + 1) * SXP + 2 * t);
            ffma2(ab, x1, pk2(w0r[k + 1]));
        }
        float h0, h1;
        un2(add2(aa, ab), h0, h1);
        *(float2*)(hbuf + 2 * lane) = make_float2(fmaxf(h0, 0.f), fmaxf(h1, 0.f));
        __syncwarp();
        // layer2: o[j] = b1[j] + sum_k h[k] * w1[k][j]
        ull oa = pk2(b1j);
        ull ob = 0;
#pragma unroll
        for (int k = 0; k < 32; k += 2) {
            ull x0 = *(const ull*)(hbuf + 2 * k);
            ffma2(oa, x0, pk2(w1r[k]));
            ull x1 = *(const ull*)(hbuf + 2 * (k + 1));
            ffma2(ob, x1, pk2(w1r[k + 1]));
        }
        float o0, o1;
        un2(add2(oa, ob), o0, o1);
        if (MODE != 2) {
            red1(accout + (size_t)r0 * FF + lane, o0);
            red1(accout + (size_t)r1 * FF + lane, o1);
        }
        *(float2*)(obuf + lane * SXP + 2 * t) =
            make_float2(fmaxf(o0, 0.f), fmaxf(o1, 0.f));
        __syncwarp();  // protect hbuf before next pass
    }

    if (MODE != 2) {
        // coalesced store of obuf (relu'd o, col-major [col][edge]) to eout[k][E]
#pragma unroll
        for (int i = 0; i < 8; i++) {
            int row = 4 * i + (lane >> 3);
            int col = (lane & 7) * 4;
            float4 v = *(const float4*)(obuf + row * SXP + col);
            *(float4*)(eout + (size_t)row * EE + base + col) = v;
        }
    } else {
        // folded heads: lane = edge
        int edge = base + lane;
        float4 a = *(const float4*)(ea + (size_t)edge * 4);
        float x0 = g_bx[0] + a.x, x1 = g_bx[1] + a.y;
        float x2 = g_bx[2] + a.z, x3 = g_bx[3] + a.w;
        float z = g_bz;
#pragma unroll
        for (int k = 0; k < 32; k++) {
            float v = obuf[k * SXP + lane];  // relu(e4)[k]
            float4 w = *(const float4*)(g_wx + k * 4);
            x0 += v * w.x;
            x1 += v * w.y;
            x2 += v * w.z;
            x3 += v * w.w;
            z += v * g_wz[k];
        }
        float nrm = sqrtf(x0 * x0 + x1 * x1 + x2 * x2 + x3 * x3);
        float inv = 1.0f / fmaxf(nrm, 1e-12f);
        *(float4*)(out + (size_t)EE + (size_t)edge * 4) =
            make_float4(x0 * inv, x1 * inv, x2 * inv, x3 * inv);
        out[edge] = 1.0f / (1.0f + expf(-z));
    }
}

#define EW_SM(K1) ((K1 * SXP + 32 * SXP + 64 + 64) * 4 * 4)

// ---------------- launch ----------------
extern "C" void kernel_launch(void* const* d_in, const int* in_sizes, int n_in,
                              void* d_out, int out_size) {
    const int* eidx = (const int*)d_in[1];
    const float* ea = (const float*)d_in[2];
    const float* beta = (const float*)d_in[3];
    const float* w10 = (const float*)d_in[4];
    const float* b10 = (const float*)d_in[5];
    const float* w11 = (const float*)d_in[6];
    const float* b11 = (const float*)d_in[7];
    const float* w20 = (const float*)d_in[8];
    const float* b20 = (const float*)d_in[9];
    const float* w21 = (const float*)d_in[10];
    const float* b21 = (const float*)d_in[11];
    const float* w30 = (const float*)d_in[12];
    const float* b30 = (const float*)d_in[13];
    const float* w31 = (const float*)d_in[14];
    const float* b31 = (const float*)d_in[15];
    const float* w40 = (const float*)d_in[16];
    const float* b40 = (const float*)d_in[17];
    const float* w41 = (const float*)d_in[18];
    const float* b41 = (const float*)d_in[19];
    const float* wl01 = (const float*)d_in[20];
    const float* bl01 = (const float*)d_in[21];
    const float* wl02 = (const float*)d_in[22];
    const float* bl02 = (const float*)d_in[23];
    const float* wl1 = (const float*)d_in[24];
    const float* bl1 = (const float*)d_in[25];
    const float* wl2 = (const float*)d_in[26];
    const float* bl2 = (const float*)d_in[27];
    float* out = (float*)d_out;

    float *acc1p, *acc2p, *acc3p, *e1p, *e2p, *e3p;
    cudaGetSymbolAddress((void**)&acc1p, g_acc1);
    cudaGetSymbolAddress((void**)&acc2p, g_acc2);
    cudaGetSymbolAddress((void**)&acc3p, g_acc3);
    cudaGetSymbolAddress((void**)&e1p, g_e1);
    cudaGetSymbolAddress((void**)&e2p, g_e2);
    cudaGetSymbolAddress((void**)&e3p, g_e3);

    static int attr_done = 0;
    if (!attr_done) {
        cudaFuncSetAttribute(k_edgew<36, 0>, cudaFuncAttributeMaxDynamicSharedMemorySize,
                             EW_SM(36));
        cudaFuncSetAttribute(k_edgew<64, 1>, cudaFuncAttributeMaxDynamicSharedMemorySize,
                             EW_SM(64));
        cudaFuncSetAttribute(k_edgew<64, 2>, cudaFuncAttributeMaxDynamicSharedMemorySize,
                             EW_SM(64));
        attr_done = 1;
    }

    const int T = 256;
    const int gridI = (NN * FF / 4 + T - 1) / T;
    const int TB = 128;
    const int gridP = (HALF_E + TB - 1) / TB;
    const int gridN = (NN + 127) / 128;
    const int gridW = EE / 128;  // 3125

    k_init<<<gridI, T>>>(beta, out, wl01, bl01, wl02, bl02, wl1, bl1, wl2, bl2);
    k_conv1<<<gridP, TB>>>(ea, eidx, w10, b10, w11, b11);

    k_node<32><<<gridN, 256>>>(acc1p, nullptr, w20, b20);
    k_edgew<36, 0><<<gridW, 128, EW_SM(36)>>>(eidx, ea, e1p, nullptr, w20 + 64 * FF, w21,
                                              b21, acc2p, e2p, out);

    k_node<64><<<gridN, 256>>>(acc2p, acc1p, w30, b30);
    k_edgew<64, 1><<<gridW, 128, EW_SM(64)>>>(eidx, ea, e2p, e1p, w30 + 128 * FF, w31, b31,
                                              acc3p, e3p, out);

    k_node<64><<<gridN, 256>>>(acc3p, acc2p, w40, b40);
    k_edgew<64, 2><<<gridW, 128, EW_SM(64)>>>(eidx, ea, e3p, e2p, w40 + 128 * FF, w41, b41,
                                              nullptr, nullptr, out);
}